// round 2
// baseline (speedup 1.0000x reference)
#include <cuda_runtime.h>

#define L 1024
#define D 64
#define OUT_ELEMS (4*16*1024*64)

// swizzled transposed-tile index: logical (row d, col-group m4 of 4 floats)
// physical float4 index within a [64][128]-float tile
__device__ __forceinline__ int sw32(int d, int m4) { return d * 32 + (m4 ^ (d & 31)); }

// ---------------------------------------------------------------------------
// Kernel 1: S = Q K^T * 0.125, masked (-10000 pre-bias), + bias -> score (raw)
// CTA: 128x128 tile, 256 threads, 8x8 micro-tile, D=64 single k-pass.
// ---------------------------------------------------------------------------
__global__ __launch_bounds__(256, 2)
void qk_kernel(const float* __restrict__ Q, const float* __restrict__ K,
               const int* __restrict__ mask, const float* __restrict__ bias,
               float* __restrict__ score)
{
    extern __shared__ float sm[];
    float* Qs = sm;          // 64 x 128 floats (32 KB), transposed+swizzled
    float* Ks = sm + 8192;   // 64 x 128 floats (32 KB)

    const int tid = threadIdx.x;
    const int tx = tid & 15, ty = tid >> 4;
    const int kt = blockIdx.x, qt = blockIdx.y, bh = blockIdx.z;
    const int b = bh >> 4, h = bh & 15;

    const float4* Qg = (const float4*)(Q + ((size_t)bh * L + qt * 128) * D);
    const float4* Kg = (const float4*)(K + ((size_t)bh * L + kt * 128) * D);

    #pragma unroll
    for (int it = 0; it < 8; it++) {
        int i = tid + it * 256;
        int m = i >> 4, dq = i & 15;
        float4 qv = Qg[m * 16 + dq];
        float4 kv = Kg[m * 16 + dq];
        int m4 = m >> 2, ml = m & 3;
        #pragma unroll
        for (int r = 0; r < 4; r++) {
            int d = dq * 4 + r;
            Qs[sw32(d, m4) * 4 + ml] = (&qv.x)[r];
            Ks[sw32(d, m4) * 4 + ml] = (&kv.x)[r];
        }
    }
    __syncthreads();

    float acc[8][8];
    #pragma unroll
    for (int i = 0; i < 8; i++)
        #pragma unroll
        for (int j = 0; j < 8; j++) acc[i][j] = 0.0f;

    const float4* Qs4 = (const float4*)Qs;
    const float4* Ks4 = (const float4*)Ks;

    #pragma unroll 8
    for (int d = 0; d < 64; d++) {
        int x = d & 31;
        float4 qa = Qs4[d * 32 + (ty ^ x)];
        float4 qb = Qs4[d * 32 + ((ty + 16) ^ x)];
        float4 ka = Ks4[d * 32 + (tx ^ x)];
        float4 kb = Ks4[d * 32 + ((tx + 16) ^ x)];
        float q[8] = {qa.x, qa.y, qa.z, qa.w, qb.x, qb.y, qb.z, qb.w};
        float k[8] = {ka.x, ka.y, ka.z, ka.w, kb.x, kb.y, kb.z, kb.w};
        #pragma unroll
        for (int i = 0; i < 8; i++)
            #pragma unroll
            for (int j = 0; j < 8; j++)
                acc[i][j] = fmaf(q[i], k[j], acc[i][j]);
    }

    const int qbase = qt * 128, kbase = kt * 128;
    #pragma unroll
    for (int ri = 0; ri < 8; ri++) {
        int qq = qbase + ((ri < 4) ? (ty * 4 + ri) : (64 + ty * 4 + ri - 4));
        const int*   mrow = mask  + (size_t)(b * L + qq) * L + kbase;
        const float* brow = bias  + (size_t)(h * L + qq) * L + kbase;
        float*       srow = score + (size_t)(bh * L + qq) * L + kbase;
        #pragma unroll
        for (int g = 0; g < 2; g++) {
            int c0 = tx * 4 + g * 64;
            int4   mv = *(const int4*)(mrow + c0);
            float4 bv = *(const float4*)(brow + c0);
            float4 ov;
            const int* mp = &mv.x; const float* bp = &bv.x; float* op = &ov.x;
            #pragma unroll
            for (int j = 0; j < 4; j++) {
                float s = acc[ri][g * 4 + j] * 0.125f;
                op[j] = (mp[j] == 0 ? -10000.0f : s) + bp[j];
            }
            *(float4*)(srow + c0) = ov;
        }
    }
}

// ---------------------------------------------------------------------------
// Kernel 2: in-place row softmax over score. One warp per row (L=1024 floats
// = 256 float4 = 8 float4 per lane), shuffle-only reductions.
// ---------------------------------------------------------------------------
__global__ __launch_bounds__(256)
void softmax_kernel(float* __restrict__ score)
{
    const int row  = (blockIdx.x << 3) + (threadIdx.x >> 5);
    const int lane = threadIdx.x & 31;
    float4* p = (float4*)(score + (size_t)row * L);

    float4 v[8];
    #pragma unroll
    for (int i = 0; i < 8; i++) v[i] = p[lane + 32 * i];

    float m = -3.4e38f;
    #pragma unroll
    for (int i = 0; i < 8; i++)
        m = fmaxf(m, fmaxf(fmaxf(v[i].x, v[i].y), fmaxf(v[i].z, v[i].w)));
    #pragma unroll
    for (int o = 16; o; o >>= 1) m = fmaxf(m, __shfl_xor_sync(0xffffffffu, m, o));

    float s = 0.0f;
    #pragma unroll
    for (int i = 0; i < 8; i++) {
        v[i].x = __expf(v[i].x - m); v[i].y = __expf(v[i].y - m);
        v[i].z = __expf(v[i].z - m); v[i].w = __expf(v[i].w - m);
        s += (v[i].x + v[i].y) + (v[i].z + v[i].w);
    }
    #pragma unroll
    for (int o = 16; o; o >>= 1) s += __shfl_xor_sync(0xffffffffu, s, o);

    float inv = __fdividef(1.0f, s);
    #pragma unroll
    for (int i = 0; i < 8; i++) {
        v[i].x *= inv; v[i].y *= inv; v[i].z *= inv; v[i].w *= inv;
        p[lane + 32 * i] = v[i];
    }
}

// ---------------------------------------------------------------------------
// Kernel 3: O = P @ V. CTA: 128 q-rows x 64 dims, 256 threads, 8x4 micro-tile,
// k-loop over L in 64-chunks with swizzled-transposed P tile.
// ---------------------------------------------------------------------------
__global__ __launch_bounds__(256, 2)
void pv_kernel(const float* __restrict__ P, const float* __restrict__ V,
               float* __restrict__ out)
{
    __shared__ float Ps[8192];   // 64 x 128, transposed+swizzled (32 KB)
    __shared__ float Vs[4096];   // 64 x 64, natural (16 KB)

    const int tid = threadIdx.x;
    const int tx = tid & 15, ty = tid >> 4;
    const int qt = blockIdx.x, bh = blockIdx.y;

    float acc[8][4];
    #pragma unroll
    for (int i = 0; i < 8; i++)
        #pragma unroll
        for (int j = 0; j < 4; j++) acc[i][j] = 0.0f;

    const float4* Vg    = (const float4*)(V + (size_t)bh * L * D);
    const float*  Pbase = P + (size_t)(bh * L + qt * 128) * L;

    for (int k0 = 0; k0 < L; k0 += 64) {
        #pragma unroll
        for (int it = 0; it < 8; it++) {
            int i = tid + it * 256;
            int m = i >> 4, kq = i & 15;
            float4 pv = *(const float4*)(Pbase + (size_t)m * L + k0 + kq * 4);
            int m4 = m >> 2, ml = m & 3;
            #pragma unroll
            for (int r = 0; r < 4; r++) {
                int k = kq * 4 + r;
                Ps[sw32(k, m4) * 4 + ml] = (&pv.x)[r];
            }
        }
        #pragma unroll
        for (int it = 0; it < 4; it++) {
            int i = tid + it * 256;
            int kl = i >> 4, dq = i & 15;
            ((float4*)Vs)[kl * 16 + dq] = Vg[(size_t)(k0 + kl) * 16 + dq];
        }
        __syncthreads();

        const float4* Ps4 = (const float4*)Ps;
        const float4* Vs4 = (const float4*)Vs;
        #pragma unroll 8
        for (int k = 0; k < 64; k++) {
            int x = k & 31;
            float4 pa = Ps4[k * 32 + (ty ^ x)];
            float4 pb = Ps4[k * 32 + ((ty + 16) ^ x)];
            float4 vv = Vs4[k * 16 + tx];
            float pr[8] = {pa.x, pa.y, pa.z, pa.w, pb.x, pb.y, pb.z, pb.w};
            const float* vp = &vv.x;
            #pragma unroll
            for (int i = 0; i < 8; i++)
                #pragma unroll
                for (int j = 0; j < 4; j++)
                    acc[i][j] = fmaf(pr[i], vp[j], acc[i][j]);
        }
        __syncthreads();
    }

    #pragma unroll
    for (int ri = 0; ri < 8; ri++) {
        int qq = qt * 128 + ((ri < 4) ? (ty * 4 + ri) : (64 + ty * 4 + ri - 4));
        float4 ov = make_float4(acc[ri][0], acc[ri][1], acc[ri][2], acc[ri][3]);
        *(float4*)(out + (size_t)(bh * L + qq) * D + tx * 4) = ov;
    }
}

// ---------------------------------------------------------------------------
extern "C" void kernel_launch(void* const* d_in, const int* in_sizes, int n_in,
                              void* d_out, int out_size)
{
    const float* Q    = (const float*)d_in[0];
    const float* K    = (const float*)d_in[1];
    const float* V    = (const float*)d_in[2];
    const int*   mask = (const int*)  d_in[3];
    const float* bias = (const float*)d_in[4];

    float* out   = (float*)d_out;
    float* score = out + OUT_ELEMS;   // tuple order: (out, score)

    cudaFuncSetAttribute(qk_kernel, cudaFuncAttributeMaxDynamicSharedMemorySize, 65536);

    qk_kernel<<<dim3(8, 8, 64), 256, 65536>>>(Q, K, mask, bias, score);
    softmax_kernel<<<8192, 256>>>(score);
    pv_kernel<<<dim3(8, 64), 256>>>(score, V, out);
}

// round 3
// speedup vs baseline: 2.2290x; 2.2290x over previous
#include <cuda_runtime.h>
#include <cstdint>

#define L 1024
#define D 64
#define NBH 64
#define OUT_ELEMS (NBH*L*D)
#define SQ 68   // padded smem row stride in floats

__device__ float g_inv_l[NBH * L];   // per-row 1/sum(exp(s)), qk -> pv

__device__ __forceinline__ uint32_t f2tf(float x) {
    uint32_t r; asm("cvt.rna.tf32.f32 %0, %1;" : "=r"(r) : "f"(x)); return r;
}

__device__ __forceinline__ void mma_tf32(float* c,
    uint32_t a0, uint32_t a1, uint32_t a2, uint32_t a3, uint32_t b0, uint32_t b1)
{
    asm("mma.sync.aligned.m16n8k8.row.col.f32.tf32.tf32.f32 "
        "{%0,%1,%2,%3}, {%4,%5,%6,%7}, {%8,%9}, {%0,%1,%2,%3};"
        : "+f"(c[0]), "+f"(c[1]), "+f"(c[2]), "+f"(c[3])
        : "r"(a0), "r"(a1), "r"(a2), "r"(a3), "r"(b0), "r"(b1));
}

// ---------------------------------------------------------------------------
// Kernel 1: per (qt, bh): full 128 x 1024 score strip.
// S = QK^T/8 (3xTF32 mma), mask (-10000 pre-bias), +bias -> score (raw).
// Also accumulates l = sum(exp(s)) per row -> g_inv_l = 1/l.
// 8 warps: warp_q = wid&3 (32 rows), warp_k = wid>>2 (64 cols of the 128 tile).
// ---------------------------------------------------------------------------
__global__ __launch_bounds__(256, 2)
void qks_kernel(const float* __restrict__ Q, const float* __restrict__ K,
                const int* __restrict__ mask, const float* __restrict__ bias,
                float* __restrict__ score)
{
    extern __shared__ float sm[];
    float* Qs   = sm;                 // 128 x 68
    float* Ks   = sm + 128 * SQ;      // 128 x 68
    float* sred = sm + 2 * 128 * SQ;  // 2 x 128

    const int tid  = threadIdx.x;
    const int lane = tid & 31, wid = tid >> 5;
    const int wq = wid & 3, wk = wid >> 2;
    const int g = lane >> 2, t = lane & 3;
    const int qt = blockIdx.x, bh = blockIdx.y;
    const int b = bh >> 4, h = bh & 15;

    // load Q tile (stays for whole strip)
    {
        const float4* Qg = (const float4*)(Q + ((size_t)bh * L + qt * 128) * D);
        #pragma unroll
        for (int it = 0; it < 8; it++) {
            int i = tid + it * 256; int r = i >> 4, dq = i & 15;
            ((float4*)(Qs + r * SQ))[dq] = Qg[r * 16 + dq];
        }
    }

    float l_run[4] = {0.f, 0.f, 0.f, 0.f};

    for (int kt = 0; kt < 8; kt++) {
        __syncthreads();
        {
            const float4* Kg = (const float4*)(K + ((size_t)bh * L + kt * 128) * D);
            #pragma unroll
            for (int it = 0; it < 8; it++) {
                int i = tid + it * 256; int r = i >> 4, dq = i & 15;
                ((float4*)(Ks + r * SQ))[dq] = Kg[r * 16 + dq];
            }
        }
        __syncthreads();

        float acc[2][8][4];
        #pragma unroll
        for (int mt = 0; mt < 2; mt++)
            #pragma unroll
            for (int nt = 0; nt < 8; nt++)
                #pragma unroll
                for (int r = 0; r < 4; r++) acc[mt][nt][r] = 0.f;

        const float* Qw = Qs + (wq * 32) * SQ;
        const float* Kw = Ks + (wk * 64) * SQ;

        #pragma unroll
        for (int kk = 0; kk < 8; kk++) {
            uint32_t ahi[2][4], alo[2][4];
            #pragma unroll
            for (int mt = 0; mt < 2; mt++)
                #pragma unroll
                for (int r = 0; r < 4; r++) {
                    int row = mt * 16 + g + (r & 1) * 8;
                    int col = kk * 8 + t + (r >> 1) * 4;
                    float x = Qw[row * SQ + col];
                    uint32_t hi = f2tf(x);
                    ahi[mt][r] = hi;
                    alo[mt][r] = f2tf(x - __uint_as_float(hi));
                }
            #pragma unroll
            for (int nt = 0; nt < 8; nt++) {
                uint32_t bhi[2], blo[2];
                #pragma unroll
                for (int r = 0; r < 2; r++) {
                    float x = Kw[(nt * 8 + g) * SQ + kk * 8 + t + r * 4];
                    uint32_t hi = f2tf(x);
                    bhi[r] = hi;
                    blo[r] = f2tf(x - __uint_as_float(hi));
                }
                #pragma unroll
                for (int mt = 0; mt < 2; mt++) {
                    mma_tf32(acc[mt][nt], ahi[mt][0], ahi[mt][1], ahi[mt][2], ahi[mt][3], blo[0], blo[1]);
                    mma_tf32(acc[mt][nt], alo[mt][0], alo[mt][1], alo[mt][2], alo[mt][3], bhi[0], bhi[1]);
                    mma_tf32(acc[mt][nt], ahi[mt][0], ahi[mt][1], ahi[mt][2], ahi[mt][3], bhi[0], bhi[1]);
                }
            }
        }

        // epilogue: scale, mask, bias, store raw s, accumulate sum(exp(s))
        const int q0 = qt * 128 + wq * 32;
        const int cp0 = kt * 64 + wk * 32;   // float2 index base of this warp's cols
        #pragma unroll
        for (int mt = 0; mt < 2; mt++)
            #pragma unroll
            for (int half = 0; half < 2; half++) {
                int row = q0 + mt * 16 + half * 8 + g;
                const int2*   mrow = (const int2*)  (mask  + ((size_t)b  * L + row) * L);
                const float2* brow = (const float2*)(bias  + ((size_t)h  * L + row) * L);
                float2*       srow = (float2*)      (score + ((size_t)bh * L + row) * L);
                float lsum = 0.f;
                #pragma unroll
                for (int nt = 0; nt < 8; nt++) {
                    int cp = cp0 + nt * 4 + t;
                    int2   mv = mrow[cp];
                    float2 bv = brow[cp];
                    float s0 = acc[mt][nt][half * 2 + 0] * 0.125f;
                    float s1 = acc[mt][nt][half * 2 + 1] * 0.125f;
                    s0 = (mv.x == 0 ? -10000.f : s0) + bv.x;
                    s1 = (mv.y == 0 ? -10000.f : s1) + bv.y;
                    srow[cp] = make_float2(s0, s1);
                    lsum += __expf(s0) + __expf(s1);
                }
                l_run[mt * 2 + half] += lsum;
            }
    }

    // reduce l over the 4 t-lanes
    #pragma unroll
    for (int li = 0; li < 4; li++) {
        l_run[li] += __shfl_xor_sync(0xffffffffu, l_run[li], 1);
        l_run[li] += __shfl_xor_sync(0xffffffffu, l_run[li], 2);
    }
    __syncthreads();
    if (t == 0) {
        #pragma unroll
        for (int li = 0; li < 4; li++) {
            int row = wq * 32 + (li >> 1) * 16 + (li & 1) * 8 + g;
            sred[wk * 128 + row] = l_run[li];
        }
    }
    __syncthreads();
    if (tid < 128) {
        float l = sred[tid] + sred[128 + tid];
        g_inv_l[(size_t)bh * L + qt * 128 + tid] = 1.0f / l;
    }
}

// ---------------------------------------------------------------------------
// Kernel 2: O = P V with P = exp(s) * inv_l computed on the fly; also writes
// the normalized score (p) back over the raw s. TF32 mma, 8 warps x 16 rows.
// ---------------------------------------------------------------------------
__global__ __launch_bounds__(256, 2)
void pv_kernel(const float* __restrict__ V, float* score, float* __restrict__ out)
{
    extern __shared__ float sm[];
    float* Ps   = sm;                           // 128 x 68
    float* Vs   = sm + 128 * SQ;                // 64 x 68
    float* sinv = sm + 128 * SQ + 64 * SQ;      // 128

    const int tid  = threadIdx.x;
    const int lane = tid & 31, wid = tid >> 5;
    const int g = lane >> 2, t = lane & 3;
    const int qt = blockIdx.x, bh = blockIdx.y;

    if (tid < 128) sinv[tid] = g_inv_l[(size_t)bh * L + qt * 128 + tid];

    float acc[8][4];
    #pragma unroll
    for (int nt = 0; nt < 8; nt++)
        #pragma unroll
        for (int r = 0; r < 4; r++) acc[nt][r] = 0.f;

    const float4* Vg = (const float4*)(V + (size_t)bh * L * D);
    float* sbase = score + ((size_t)bh * L + qt * 128) * L;

    for (int c = 0; c < 16; c++) {      // k-chunks of 64
        __syncthreads();
        // P loader: normalize on the fly, write p to gmem, stage into smem
        #pragma unroll
        for (int it = 0; it < 8; it++) {
            int i = tid + it * 256; int r = i >> 4, kq = i & 15;
            float* sp = sbase + (size_t)r * L + c * 64 + kq * 4;
            float4 s4 = *(float4*)sp;
            float il = sinv[r];
            float4 p4;
            p4.x = __expf(s4.x) * il; p4.y = __expf(s4.y) * il;
            p4.z = __expf(s4.z) * il; p4.w = __expf(s4.w) * il;
            *(float4*)sp = p4;
            ((float4*)(Ps + r * SQ))[kq] = p4;
        }
        // V loader: rows c*64 .. c*64+63
        #pragma unroll
        for (int it = 0; it < 4; it++) {
            int i = tid + it * 256; int r = i >> 4, dq = i & 15;
            ((float4*)(Vs + r * SQ))[dq] = Vg[(size_t)(c * 64 + r) * 16 + dq];
        }
        __syncthreads();

        const float* Pw = Ps + (wid * 16) * SQ;
        #pragma unroll
        for (int kk = 0; kk < 8; kk++) {
            uint32_t a[4];
            #pragma unroll
            for (int r = 0; r < 4; r++) {
                int row = g + (r & 1) * 8;
                int col = kk * 8 + t + (r >> 1) * 4;
                a[r] = f2tf(Pw[row * SQ + col]);
            }
            #pragma unroll
            for (int nt = 0; nt < 8; nt++) {
                uint32_t b0 = f2tf(Vs[(kk * 8 + t)     * SQ + nt * 8 + g]);
                uint32_t b1 = f2tf(Vs[(kk * 8 + t + 4) * SQ + nt * 8 + g]);
                mma_tf32(acc[nt], a[0], a[1], a[2], a[3], b0, b1);
            }
        }
    }

    #pragma unroll
    for (int half = 0; half < 2; half++) {
        int row = qt * 128 + wid * 16 + half * 8 + g;
        float2* orow = (float2*)(out + ((size_t)bh * L + row) * D);
        #pragma unroll
        for (int nt = 0; nt < 8; nt++)
            orow[nt * 4 + t] = make_float2(acc[nt][half * 2], acc[nt][half * 2 + 1]);
    }
}

// ---------------------------------------------------------------------------
extern "C" void kernel_launch(void* const* d_in, const int* in_sizes, int n_in,
                              void* d_out, int out_size)
{
    const float* Q    = (const float*)d_in[0];
    const float* K    = (const float*)d_in[1];
    const float* V    = (const float*)d_in[2];
    const int*   mask = (const int*)  d_in[3];
    const float* bias = (const float*)d_in[4];

    float* out   = (float*)d_out;
    float* score = out + OUT_ELEMS;   // tuple order: (out, score)

    const int qk_smem = (2 * 128 * SQ + 256) * 4;            // 70656 B
    const int pv_smem = (128 * SQ + 64 * SQ + 128) * 4;      // 52736 B
    cudaFuncSetAttribute(qks_kernel, cudaFuncAttributeMaxDynamicSharedMemorySize, qk_smem);
    cudaFuncSetAttribute(pv_kernel,  cudaFuncAttributeMaxDynamicSharedMemorySize, pv_smem);

    qks_kernel<<<dim3(8, 64), 256, qk_smem>>>(Q, K, mask, bias, score);
    pv_kernel <<<dim3(8, 64), 256, pv_smem>>>(V, score, out);
}